// round 5
// baseline (speedup 1.0000x reference)
#include <cuda_runtime.h>

#define NH 6
#define HD 32
#define NTOK 64
#define HIDDEN 512
#define TBL 225
#define HW 65536
#define ST 68

typedef unsigned long long ull;

// packed fp32x2 ops (Blackwell; ptxas never auto-emits these)
#define FMA2(d, a, b, c) \
    asm("fma.rn.f32x2 %0, %1, %2, %3;" : "=l"(d) : "l"(a), "l"(b), "l"(c))
#define PACK2(d, x) \
    asm("mov.b64 %0, {%1, %1};" : "=l"(d) : "f"(x))
#define UNPACK2(lo, hi, v) \
    asm("mov.b64 {%0, %1}, %2;" : "=f"(lo), "=f"(hi) : "l"(v))

union F4U {
    float4 f4;
    float f[4];
    ull u[2];
};

// device-global scratch (no allocations allowed)
__device__ float g_bt[TBL * NH];
__device__ float g_hscale[NH];
__device__ float g_bias[NH * NTOK * NTOK];

// ---------------------------------------------------------------------------
// Kernel 0a: CPB MLP, one block per table row (225 blocks) + head scales.
// ---------------------------------------------------------------------------
__global__ void __launch_bounds__(128) bias_mlp_kernel(
    const float* __restrict__ table,
    const float* __restrict__ logit_scale,
    const float* __restrict__ w1,
    const float* __restrict__ b1,
    const float* __restrict__ w2) {
    const int row = blockIdx.x;
    const int tid = threadIdx.x;

    if (row == 0 && tid < NH) {
        const float LOGIT_MAX = 4.605170185988091368f; // log(100)
        g_hscale[tid] = expf(fminf(logit_scale[tid], LOGIT_MAX)) * rsqrtf((float)HD);
    }

    const float t0 = table[row * 2 + 0];
    const float t1 = table[row * 2 + 1];
    float acc[NH];
#pragma unroll
    for (int h = 0; h < NH; h++) acc[h] = 0.f;

    for (int j = tid; j < HIDDEN; j += 128) {
        float hv = fmaf(t0, w1[j], fmaf(t1, w1[HIDDEN + j], b1[j]));
        hv = fmaxf(hv, 0.f);
#pragma unroll
        for (int h = 0; h < NH; h++) acc[h] = fmaf(hv, w2[j * NH + h], acc[h]);
    }

#pragma unroll
    for (int h = 0; h < NH; h++) {
#pragma unroll
        for (int o = 16; o > 0; o >>= 1)
            acc[h] += __shfl_xor_sync(0xffffffffu, acc[h], o);
    }
    __shared__ float red[4][NH];
    const int warp = tid >> 5;
    if ((tid & 31) == 0) {
#pragma unroll
        for (int h = 0; h < NH; h++) red[warp][h] = acc[h];
    }
    __syncthreads();
    if (tid == 0) {
#pragma unroll
        for (int h = 0; h < NH; h++)
            g_bt[row * NH + h] = red[0][h] + red[1][h] + red[2][h] + red[3][h];
    }
}

// ---------------------------------------------------------------------------
// Kernel 0b: expand bias -> g_bias[h][n][m] = 16*sigmoid(bt[index[n][m]][h])
// ---------------------------------------------------------------------------
__global__ void bias_gather_kernel(const int* __restrict__ index) {
    int gid = blockIdx.x * blockDim.x + threadIdx.x;
    if (gid >= NH * NTOK * NTOK) return;
    int h = gid >> 12;
    int nm = gid & 4095;
    int r = index[nm];
    float bv = g_bt[r * NH + h];
    g_bias[gid] = 16.f / (1.f + __expf(-bv));
}

// ---------------------------------------------------------------------------
// Main kernel: one CTA per (window, head). 64 threads, 8 CTAs/SM.
//  8x8 register tiles (crossbar-balanced), f32x2 FMA, P-buffer aliased on q/k.
// ---------------------------------------------------------------------------
__global__ void __launch_bounds__(64, 8) win_attn_kernel(
    const float* __restrict__ qkv,
    const float* __restrict__ mask,
    const float* __restrict__ bias,
    float* __restrict__ out)
{
    __shared__ __align__(16) float pool[3 * HD * ST];
    float* const sq = pool;                 // [32][68]
    float* const sk = pool + HD * ST;       // [32][68]
    float* const sv = pool + 2 * HD * ST;   // [32][68]
    float* const ss = pool;                 // [64][68] aliases sq+sk (exact fit)

    const int tid = threadIdx.x;
    const int bid = blockIdx.x;
    const int h = bid % NH;
    const int b_ = bid / NH;           // 0..2047
    const int b = b_ >> 10;            // batch
    const int w = b_ & 1023;           // window id within image
    const int wy = w >> 5, wx = w & 31;
    // roll(-4,-4): window pixel (i,j) <- original ((wy*8+i+4)&255, (wx*8+j+4)&255)
    const int y0 = wy * 8 + 4;
    const int x0 = wx * 8 + 4;

    // channel = t*384 + b*192 + h*32 + d   (qkv is (3,B,192,H,W))
    const int chbase = b * 192 + h * 32;

    // ---- load q,k,v: 1536 float4 loads (24/thread), into smem [d][n] ----
#pragma unroll
    for (int k4 = 0; k4 < 24; k4++) {
        int idx4 = tid + k4 * 64;
        int t = idx4 >> 9;              // 0..2
        int d = (idx4 >> 4) & 31;
        int q16 = idx4 & 15;            // 16 float4 per (t,d) plane
        int i = q16 >> 1;               // window row 0..7
        int j0 = (q16 & 1) << 2;        // 0 or 4
        int y = (y0 + i) & 255;
        int x = (x0 + j0) & 255;        // 4-aligned, never splits across wrap
        const float4 val = *(const float4*)(qkv + (chbase + t * 384 + d) * HW + y * 256 + x);
        float* dst = (t == 0 ? sq : (t == 1 ? sk : sv)) + d * ST + i * 8 + j0;
        *(float4*)dst = val;
    }
    __syncthreads();

    const float scale = g_hscale[h];
    const float* mask_w = mask + w * 4096;
    const float* bias_h = bias + h * 4096;

    const int mi = tid & 7;
    const int m0 = mi * 4;              // m set = {m0..m0+3} U {m0+32..m0+35}
    const int ng = tid >> 3;
    const int n0 = ng * 8;              // 8 consecutive n rows (one window row)

    // ---- phase 1: S = q.k over 8n x 8m tile ----
    ull acc2[8][4];
#pragma unroll
    for (int a = 0; a < 8; a++)
#pragma unroll
        for (int c = 0; c < 4; c++) acc2[a][c] = 0ull;

    {
        const float* pq = sq + n0;
        const float* pk = sk + m0;
#pragma unroll 2
        for (int d = 0; d < 32; d++) {
            F4U qa0, qa1, kb0, kb1;
            qa0.f4 = *(const float4*)(pq + d * ST);        // broadcast (8 lanes same)
            qa1.f4 = *(const float4*)(pq + d * ST + 4);
            kb0.f4 = *(const float4*)(pk + d * ST);        // conflict-free
            kb1.f4 = *(const float4*)(pk + d * ST + 32);
#pragma unroll
            for (int a = 0; a < 4; a++) {
                ull qp;
                PACK2(qp, qa0.f[a]);
                FMA2(acc2[a][0], qp, kb0.u[0], acc2[a][0]);
                FMA2(acc2[a][1], qp, kb0.u[1], acc2[a][1]);
                FMA2(acc2[a][2], qp, kb1.u[0], acc2[a][2]);
                FMA2(acc2[a][3], qp, kb1.u[1], acc2[a][3]);
            }
#pragma unroll
            for (int a = 0; a < 4; a++) {
                ull qp;
                PACK2(qp, qa1.f[a]);
                FMA2(acc2[4 + a][0], qp, kb0.u[0], acc2[4 + a][0]);
                FMA2(acc2[4 + a][1], qp, kb0.u[1], acc2[4 + a][1]);
                FMA2(acc2[4 + a][2], qp, kb1.u[0], acc2[4 + a][2]);
                FMA2(acc2[4 + a][3], qp, kb1.u[1], acc2[4 + a][3]);
            }
        }
    }
    __syncthreads();   // all reads of sq/sk complete before P overwrites them

    // ---- epilogue: bias + mask + register softmax, write P into ss ----
    {
        // software-pipelined bias/mask loads (row a+1 prefetched during row a)
        F4U mv0, mv1, bv0, bv1;
        mv0.f4 = *(const float4*)(mask_w + n0 * 64 + m0);
        mv1.f4 = *(const float4*)(mask_w + n0 * 64 + m0 + 32);
        bv0.f4 = *(const float4*)(bias_h + n0 * 64 + m0);
        bv1.f4 = *(const float4*)(bias_h + n0 * 64 + m0 + 32);
#pragma unroll
        for (int a = 0; a < 8; a++) {
            const int n = n0 + a;
            F4U cm0 = mv0, cm1 = mv1, cb0 = bv0, cb1 = bv1;
            if (a < 7) {
                mv0.f4 = *(const float4*)(mask_w + (n + 1) * 64 + m0);
                mv1.f4 = *(const float4*)(mask_w + (n + 1) * 64 + m0 + 32);
                bv0.f4 = *(const float4*)(bias_h + (n + 1) * 64 + m0);
                bv1.f4 = *(const float4*)(bias_h + (n + 1) * 64 + m0 + 32);
            }
            float s[8];
#pragma unroll
            for (int c = 0; c < 2; c++) {
                float lo, hi;
                UNPACK2(lo, hi, acc2[a][c]);
                s[2 * c]     = fmaf(lo, scale, cb0.f[2 * c] + cm0.f[2 * c]);
                s[2 * c + 1] = fmaf(hi, scale, cb0.f[2 * c + 1] + cm0.f[2 * c + 1]);
            }
#pragma unroll
            for (int c = 0; c < 2; c++) {
                float lo, hi;
                UNPACK2(lo, hi, acc2[a][2 + c]);
                s[4 + 2 * c]     = fmaf(lo, scale, cb1.f[2 * c] + cm1.f[2 * c]);
                s[4 + 2 * c + 1] = fmaf(hi, scale, cb1.f[2 * c + 1] + cm1.f[2 * c + 1]);
            }
            float mx = -1e30f;
#pragma unroll
            for (int c = 0; c < 8; c++) mx = fmaxf(mx, s[c]);
            mx = fmaxf(mx, __shfl_xor_sync(0xffffffffu, mx, 1));
            mx = fmaxf(mx, __shfl_xor_sync(0xffffffffu, mx, 2));
            mx = fmaxf(mx, __shfl_xor_sync(0xffffffffu, mx, 4));
            float sum = 0.f;
#pragma unroll
            for (int c = 0; c < 8; c++) {
                s[c] = __expf(s[c] - mx);
                sum += s[c];
            }
            sum += __shfl_xor_sync(0xffffffffu, sum, 1);
            sum += __shfl_xor_sync(0xffffffffu, sum, 2);
            sum += __shfl_xor_sync(0xffffffffu, sum, 4);
            const float rinv = 1.f / sum;
            float4 p0 = make_float4(s[0] * rinv, s[1] * rinv, s[2] * rinv, s[3] * rinv);
            float4 p1 = make_float4(s[4] * rinv, s[5] * rinv, s[6] * rinv, s[7] * rinv);
            *(float4*)&ss[n * ST + m0] = p0;
            *(float4*)&ss[n * ST + m0 + 32] = p1;
        }
    }
    __syncthreads();

    // ---- phase 3: O[d][n] = V[d][:] . P[n][:]^T, tile 8n x 4d ----
    // d in {d0, d0+8, d0+16, d0+24}, d0 = mi -> conflict-free V loads.
    {
        ull o2[8][4];
#pragma unroll
        for (int a = 0; a < 8; a++)
#pragma unroll
            for (int i = 0; i < 4; i++) o2[a][i] = 0ull;

        const int d0 = mi;
        const float* pv = sv + d0 * ST;
        const float* pp = ss + n0 * ST;
#pragma unroll 2
        for (int mb = 0; mb < 16; mb++) {
            const int m = mb * 4;
            F4U v[4], p[8];
#pragma unroll
            for (int i = 0; i < 4; i++) v[i].f4 = *(const float4*)(pv + i * 8 * ST + m);
#pragma unroll
            for (int a = 0; a < 8; a++) p[a].f4 = *(const float4*)(pp + a * ST + m);
#pragma unroll
            for (int a = 0; a < 8; a++)
#pragma unroll
                for (int i = 0; i < 4; i++) {
                    FMA2(o2[a][i], v[i].u[0], p[a].u[0], o2[a][i]);
                    FMA2(o2[a][i], v[i].u[1], p[a].u[1], o2[a][i]);
                }
        }

        // store: thread's 8 n-rows = one full window row ng; roll cancels.
        const int y = (y0 + ng) & 255;
        const int xa = x0 & 255;           // cols 0..3 of the window row
        const int xb = (x0 + 4) & 255;     // cols 4..7 (may wrap, 4-aligned)
#pragma unroll
        for (int i = 0; i < 4; i++) {
            const int d = d0 + i * 8;
            float ov[8];
#pragma unroll
            for (int a = 0; a < 8; a++) {
                float lo, hi;
                UNPACK2(lo, hi, o2[a][i]);
                ov[a] = lo + hi;
            }
            float* orow = out + (chbase + d) * HW + y * 256;
            *(float4*)(orow + xa) = make_float4(ov[0], ov[1], ov[2], ov[3]);
            *(float4*)(orow + xb) = make_float4(ov[4], ov[5], ov[6], ov[7]);
        }
    }
}

// ---------------------------------------------------------------------------
extern "C" void kernel_launch(void* const* d_in, const int* in_sizes, int n_in,
                              void* d_out, int out_size) {
    const float* qkv         = (const float*)d_in[0];
    const float* table       = (const float*)d_in[1];
    const int*   index       = (const int*)  d_in[2];
    const float* mask        = (const float*)d_in[3];
    const float* logit_scale = (const float*)d_in[4];
    const float* w1          = (const float*)d_in[5];
    const float* b1          = (const float*)d_in[6];
    const float* w2          = (const float*)d_in[7];
    float* out = (float*)d_out;

    cudaFuncSetAttribute(win_attn_kernel,
                         cudaFuncAttributePreferredSharedMemoryCarveout, 100);

    bias_mlp_kernel<<<TBL, 128>>>(table, logit_scale, w1, b1, w2);
    bias_gather_kernel<<<96, 256>>>(index);

    float* d_bias = nullptr;
    cudaGetSymbolAddress((void**)&d_bias, g_bias);
    win_attn_kernel<<<2 * 1024 * NH, 64>>>(qkv, mask, d_bias, out);
    (void)in_sizes; (void)n_in; (void)out_size;
}